// round 11
// baseline (speedup 1.0000x reference)
#include <cuda_runtime.h>
#include <cstdint>

#define GS 96
#define CC 64               // 8*8 elements per block
#define B_DIM 64
#define THREADS 128
#define WARPS 4
#define TT 8                // tile: TT x TT (i,j) pairs per CTA
#define NT (GS / TT)        // 12 tiles per dimension

// 256-bit streaming store (sm_100+), .cs = evict-first streaming policy.
__device__ __forceinline__ void st256_cs(float* p, float4 a, float4 b) {
    asm volatile(
        "st.global.cs.v8.b32 [%0], {%1,%2,%3,%4,%5,%6,%7,%8};"
        :: "l"(p),
           "r"(__float_as_uint(a.x)), "r"(__float_as_uint(a.y)),
           "r"(__float_as_uint(a.z)), "r"(__float_as_uint(a.w)),
           "r"(__float_as_uint(b.x)), "r"(__float_as_uint(b.y)),
           "r"(__float_as_uint(b.z)), "r"(__float_as_uint(b.w))
        : "memory");
}

// out[b][i][j][c][k]: out[...][c][0] = x[b][i][c], out[...][c][1] = x[b][j][c]
// Per (b,i,j): 128 floats, pair-interleaved (xi[0],xj[0],xi[1],xj[1],...)
//
// R7 tiling (8x8 (i,j) per CTA, 36 MB reads) with 32B-per-thread layout and
// single 256-bit streaming store per row-chunk: halves STG count vs R7.
__global__ __launch_bounds__(THREADS) void gcom_kernel(const float* __restrict__ x,
                                                       float* __restrict__ out) {
    const int blk = blockIdx.x;              // 0 .. 64*144-1
    const int b   = blk / (NT * NT);
    const int rem = blk - b * (NT * NT);
    const int i0  = (rem / NT) * TT;
    const int j0  = (rem - (rem / NT) * NT) * TT;

    // Stage 8 i-rows + 8 j-rows (2 KB each)
    __shared__ float xi_s[TT * CC];
    __shared__ float xj_s[TT * CC];
    {
        const float4* si =
            reinterpret_cast<const float4*>(x + ((size_t)b * GS + i0) * CC);
        const float4* sj =
            reinterpret_cast<const float4*>(x + ((size_t)b * GS + j0) * CC);
        reinterpret_cast<float4*>(xi_s)[threadIdx.x] = __ldg(si + threadIdx.x);
        reinterpret_cast<float4*>(xj_s)[threadIdx.x] = __ldg(sj + threadIdx.x);
    }
    __syncthreads();

    // 32B-per-thread layout: half-warp hw covers pair-row jj = wid + 4*hw;
    // lane pos (0..15) writes bytes [pos*32, pos*32+32) of that 512B row,
    // i.e. c-values 4*pos .. 4*pos+3.
    const int lane = threadIdx.x & 31;
    const int wid  = threadIdx.x >> 5;       // 0..3
    const int hw   = lane >> 4;              // 0..1
    const int pos  = lane & 15;              // 0..15
    const int jj   = wid + 4 * hw;           // 0..7

    const float4* __restrict__ xi4 = reinterpret_cast<const float4*>(xi_s);
    const float4 xjv = reinterpret_cast<const float4*>(xj_s)[jj * 16 + pos];

    float* __restrict__ ob = out
        + (((size_t)b * GS + i0) * GS + (j0 + jj)) * 2 * CC   // row base
        + pos * 8;                                            // 32B chunk

    #pragma unroll
    for (int ii = 0; ii < TT; ii++) {
        const float4 xiv = xi4[ii * 16 + pos];
        float4 lo, hi;   // interleaved pairs (xi[c], xj[c])
        lo.x = xiv.x; lo.y = xjv.x; lo.z = xiv.y; lo.w = xjv.y;
        hi.x = xiv.z; hi.y = xjv.z; hi.z = xiv.w; hi.w = xjv.w;
        st256_cs(ob + (size_t)ii * GS * 2 * CC, lo, hi);      // one STG.256 per row-chunk
    }
}

extern "C" void kernel_launch(void* const* d_in, const int* in_sizes, int n_in,
                              void* d_out, int out_size) {
    const float* x = (const float*)d_in[0];
    float* out = (float*)d_out;
    gcom_kernel<<<B_DIM * NT * NT, THREADS>>>(x, out);
}

// round 12
// speedup vs baseline: 1.0372x; 1.0372x over previous
#include <cuda_runtime.h>
#include <cstdint>

#define GS 96
#define CC 64               // 8*8 elements per block
#define B_DIM 64
#define THREADS 128
#define WARPS 4
#define TT 8                // tile: TT x TT (i,j) pairs per CTA
#define NT (GS / TT)        // 12 tiles per dimension

// out[b][i][j][c][k]: out[...][c][0] = x[b][i][c], out[...][c][1] = x[b][j][c]
// Per (b,i,j): 128 floats, pair-interleaved (xi[0],xj[0],xi[1],xj[1],...)
//
// FINAL (session optimum, reproduced twice at 45.536 us):
//  - 8x8 (i,j) tile per CTA: input reads cut to 36 MB (vs 151 MB naive)
//  - 4 KB smem staging, conflict-free float2 reads, xj hoisted to registers
//  - inner loop: 2x STG.E.128 with .cs (evict-first streaming) per thread
//  - grid 9216 x 128 thr: 87% occupancy, regs=32
// Measured at the pure-write HBM3e ceiling: ~6.6 TB/s steady-state drain
// (302 MB output / 45.5 us, ~83% of 8 TB/s spec). Verified non-binding:
// occupancy (56% run holds same DRAM%), store width, store count, L2
// policy alternatives, LTS traffic, issue rate.
__global__ __launch_bounds__(THREADS) void gcom_kernel(const float* __restrict__ x,
                                                       float* __restrict__ out) {
    const int blk = blockIdx.x;              // 0 .. 64*144-1
    const int b   = blk / (NT * NT);
    const int rem = blk - b * (NT * NT);
    const int i0  = (rem / NT) * TT;
    const int j0  = (rem - (rem / NT) * NT) * TT;

    // Stage 8 i-rows + 8 j-rows (2 KB each)
    __shared__ float xi_s[TT * CC];
    __shared__ float xj_s[TT * CC];
    {
        const float4* si =
            reinterpret_cast<const float4*>(x + ((size_t)b * GS + i0) * CC);
        const float4* sj =
            reinterpret_cast<const float4*>(x + ((size_t)b * GS + j0) * CC);
        reinterpret_cast<float4*>(xi_s)[threadIdx.x] = __ldg(si + threadIdx.x);
        reinterpret_cast<float4*>(xj_s)[threadIdx.x] = __ldg(sj + threadIdx.x);
    }
    __syncthreads();

    const int quad = threadIdx.x & 31;   // float4 index within a pair-row (32*16B = 512B)
    const int wid  = threadIdx.x >> 5;   // warp id 0..3 -> jj stride

    const float2* __restrict__ xi2 = reinterpret_cast<const float2*>(xi_s);
    const float2* __restrict__ xj2 = reinterpret_cast<const float2*>(xj_s);

    // Each warp owns jj = wid and jj = wid + 4; hoist those xj pairs to regs.
    const float2 xjv0 = xj2[wid * 32 + quad];
    const float2 xjv1 = xj2[(wid + WARPS) * 32 + quad];

    float4* __restrict__ ob =
        reinterpret_cast<float4*>(out) + (((size_t)b * GS + i0) * GS + j0) * 32;

    #pragma unroll
    for (int ii = 0; ii < TT; ii++) {
        const float2 xiv = xi2[ii * 32 + quad];
        float4* __restrict__ op = ob + (size_t)ii * GS * 32;

        float4 v0, v1;
        v0.x = xiv.x; v0.y = xjv0.x; v0.z = xiv.y; v0.w = xjv0.y;
        v1.x = xiv.x; v1.y = xjv1.x; v1.z = xiv.y; v1.w = xjv1.y;
        __stcs(op + (size_t)wid * 32 + quad,           v0);  // streaming, evict-first
        __stcs(op + (size_t)(wid + WARPS) * 32 + quad, v1);
    }
}

extern "C" void kernel_launch(void* const* d_in, const int* in_sizes, int n_in,
                              void* d_out, int out_size) {
    const float* x = (const float*)d_in[0];
    float* out = (float*)d_out;
    gcom_kernel<<<B_DIM * NT * NT, THREADS>>>(x, out);
}